// round 10
// baseline (speedup 1.0000x reference)
#include <cuda_runtime.h>

// conv2d 4096x4096 (fp32) * 15x15 VALID + bias -> 4082x4082 (fp32)
// R10: RY=2 with carried input-row window (each ky loads ONE new row feeding
//      2x FMAs), phase-shifted dual accumulators (zero packs), FFMA2,
//      ping-pong windows across ky, 2 blocks/SM (128-reg budget).

#define H 4096
#define W 4096
#define KH 15
#define KW 15
#define OH 4082
#define OW 4082

#define BX 192          // 16 threads * RX=12
#define BY 32           // 16 thread-rows * RY=2
#define NT 256
#define RX 12           // 48B lane stride: odd multiple of 16B -> conflict-free

#define IN_H (BY + KH - 1)          // 46
#define SROW 208                    // pad 192+14 -> 208 (52 float4)

typedef unsigned long long ull;

__device__ __forceinline__ ull pack2(float lo, float hi) {
    ull r; asm("mov.b64 %0, {%1, %2};" : "=l"(r) : "f"(lo), "f"(hi)); return r;
}
__device__ __forceinline__ void unpack2(ull v, float& lo, float& hi) {
    asm("mov.b64 {%0, %1}, %2;" : "=f"(lo), "=f"(hi) : "l"(v));
}
__device__ __forceinline__ ull fma2(ull a, ull b, ull c) {
    ull d; asm("fma.rn.f32x2 %0, %1, %2, %3;" : "=l"(d) : "l"(a), "l"(b), "l"(c)); return d;
}

// input-row window: 13 aligned even pairs P[0..12] (P[12] only needs 8B)
struct Win {
    ulonglong2 v[6];
    ull v6;
};
__device__ __forceinline__ ull getP(const Win& w, int p) {
    return (p == 12) ? w.v6 : ((p & 1) ? w.v[p >> 1].y : w.v[p >> 1].x);
}
__device__ __forceinline__ void loadWin(Win& w, const float* row) {
    const ulonglong2* r = (const ulonglong2*)row;
    #pragma unroll
    for (int t = 0; t < 6; ++t) w.v[t] = r[t];
    w.v6 = *(const ull*)(row + 24);
}

// One ky step: consume `cur` (row oy+ky) and `nxt` (row oy+ky+1, loaded here).
__device__ __forceinline__ void ky_step(Win& cur, Win& nxt,
                                        const float* rowN, const ull* wrow,
                                        ull (&accA)[2][6], ull (&accB)[2][7]) {
    const ulonglong2* rn = (const ulonglong2*)rowN;
    nxt.v[0] = rn[0]; nxt.v[1] = rn[1]; nxt.v[2] = rn[2]; nxt.v[3] = rn[3];
    #pragma unroll
    for (int c = 0; c < 8; ++c) {
        if (c == 0) nxt.v[4] = rn[4];
        if (c == 2) nxt.v[5] = rn[5];
        if (c == 4) nxt.v6 = *(const ull*)(rowN + 24);
        const ulonglong2 wp = *(const ulonglong2*)(wrow + 2 * c);  // (w2c, w2c+1)
        // i=0 : data long resident
        #pragma unroll
        for (int j = 0; j < 6; ++j)
            accA[0][j] = fma2(wp.x, getP(cur, j + c), accA[0][j]);
        if (c < 7) {
            #pragma unroll
            for (int j = 0; j < 7; ++j)
                accB[0][j] = fma2(wp.y, getP(cur, j + c), accB[0][j]);
        }
        // i=1 : freshly loaded row (comes after i=0 FMAs -> latency covered)
        #pragma unroll
        for (int j = 0; j < 6; ++j)
            accA[1][j] = fma2(wp.x, getP(nxt, j + c), accA[1][j]);
        if (c < 7) {
            #pragma unroll
            for (int j = 0; j < 7; ++j)
                accB[1][j] = fma2(wp.y, getP(nxt, j + c), accB[1][j]);
        }
    }
}

__global__ __launch_bounds__(NT, 2)
void conv2d_r10_kernel(const float* __restrict__ X,
                       const float* __restrict__ Wt,
                       const float* __restrict__ bias,
                       float* __restrict__ out)
{
    __shared__ __align__(16) float sX[IN_H][SROW];
    __shared__ __align__(16) ull  sWp[KH * 16];   // (w,w) pairs, rows padded to 16

    const int tid = threadIdx.x;
    const int bx = blockIdx.x * BX;
    const int by = blockIdx.y * BY;

    // ---- stage weight pairs ----
    if (tid < KH * 16) {
        int r = tid >> 4, c = tid & 15;
        float w = (c < KW) ? Wt[r * KW + c] : 0.f;
        sWp[tid] = pack2(w, w);
    }

    // ---- stage input tile: 46 rows x 208 cols, float4, guarded ----
    const int NV = IN_H * (SROW / 4);     // 46*52 = 2392
    for (int idx = tid; idx < NV; idx += NT) {
        int r  = idx / (SROW / 4);
        int c4 = idx - r * (SROW / 4);
        int gr = by + r;
        int gc = bx + c4 * 4;
        float4 v = make_float4(0.f, 0.f, 0.f, 0.f);
        if (gr < H) {
            const float* src = X + (long)gr * W + gc;
            if (gc + 3 < W) v = *(const float4*)src;
            else {
                if (gc + 0 < W) v.x = src[0];
                if (gc + 1 < W) v.y = src[1];
                if (gc + 2 < W) v.z = src[2];
                if (gc + 3 < W) v.w = src[3];
            }
        }
        *(float4*)&sX[r][c4 * 4] = v;
    }
    __syncthreads();

    const int tx = tid & 15;
    const int ty = tid >> 4;
    const int ox = tx * RX;
    const int oy = ty * 2;
    const float b0 = bias[0];

    ull accA[2][6];
    ull accB[2][7];
    {
        const ull bb = pack2(b0, b0);
        #pragma unroll
        for (int i = 0; i < 2; ++i) {
            #pragma unroll
            for (int j = 0; j < 6; ++j) accA[i][j] = bb;
            #pragma unroll
            for (int j = 0; j < 7; ++j) accB[i][j] = 0ull;
        }
    }

    Win A, B;
    loadWin(A, &sX[oy][ox]);
    const float* rowN = &sX[oy + 1][ox];
    const ull* wrow = sWp;

    // 15 ky steps = 7 ping-pong pairs + 1 final
    #pragma unroll 1
    for (int it = 0; it < 7; ++it) {
        ky_step(A, B, rowN, wrow, accA, accB);
        rowN += SROW; wrow += 16;
        ky_step(B, A, rowN, wrow, accA, accB);
        rowN += SROW; wrow += 16;
    }
    ky_step(A, B, rowN, wrow, accA, accB);   // ky = 14

    // ---- epilogue: recombine phases, guarded float2 stores ----
    #pragma unroll
    for (int i = 0; i < 2; ++i) {
        const int orow = by + oy + i;
        if (orow >= OH) continue;
        float* orp = out + (long)orow * OW;
        float alo[6], ahi[6], blo[7], bhi[7];
        #pragma unroll
        for (int j = 0; j < 6; ++j) unpack2(accA[i][j], alo[j], ahi[j]);
        #pragma unroll
        for (int j = 0; j < 7; ++j) unpack2(accB[i][j], blo[j], bhi[j]);
        #pragma unroll
        for (int j = 0; j < 6; ++j) {
            int ocol = bx + ox + 2 * j;      // even; OW even -> pair fully in or out
            if (ocol < OW) {
                float2 st;
                st.x = alo[j] + bhi[j];          // o_{2j}  (bias pre-folded in accA)
                st.y = ahi[j] + blo[j + 1];      // o_{2j+1}
                *(float2*)(orp + ocol) = st;
            }
        }
    }
}

extern "C" void kernel_launch(void* const* d_in, const int* in_sizes, int n_in,
                              void* d_out, int out_size)
{
    const float* X  = (const float*)d_in[0];
    const float* Wt = (const float*)d_in[1];
    const float* bs = (const float*)d_in[2];
    float* out = (float*)d_out;

    dim3 grid((OW + BX - 1) / BX, (OH + BY - 1) / BY);   // 22 x 128
    conv2d_r10_kernel<<<grid, NT>>>(X, Wt, bs, out);
}

// round 11
// speedup vs baseline: 1.1119x; 1.1119x over previous
#include <cuda_runtime.h>

// conv2d 4096x4096 (fp32) * 15x15 VALID + bias -> 4082x4082 (fp32)
// R11: R8 shape (RY=1, RX=12, 256thr) with a fully software-pipelined rolling
//      window: current-row tail loaded at c=0/1/2 (>=2-step lead), NEXT row's
//      head prefetched at c=3..6 (ping-pong) -> no ky-boundary LDS burst.
//      3 blocks/SM (84-reg budget) gives ptxas room to keep the schedule.

#define H 4096
#define W 4096
#define KH 15
#define KW 15
#define OH 4082
#define OW 4082

#define BX 192          // 16 threads * RX=12
#define BY 16
#define NT 256
#define RX 12           // 48B lane stride: odd multiple of 16B -> conflict-free

#define IN_H (BY + KH - 1)          // 30
#define IN_HP 31                    // +1 pad row: last-ky dead prefetch stays in bounds
#define SROW 208                    // pad 192+14 -> 208 (52 float4)

typedef unsigned long long ull;

__device__ __forceinline__ ull pack2(float lo, float hi) {
    ull r; asm("mov.b64 %0, {%1, %2};" : "=l"(r) : "f"(lo), "f"(hi)); return r;
}
__device__ __forceinline__ void unpack2(ull v, float& lo, float& hi) {
    asm("mov.b64 {%0, %1}, %2;" : "=f"(lo), "=f"(hi) : "l"(v));
}
__device__ __forceinline__ ull fma2(ull a, ull b, ull c) {
    ull d; asm("fma.rn.f32x2 %0, %1, %2, %3;" : "=l"(d) : "l"(a), "l"(b), "l"(c)); return d;
}

// head = P0..P7 of a row (first 16 floats)
struct Head { ulonglong2 h[4]; };

__device__ __forceinline__ ull getP(const Head& Hh, const ulonglong2& v4,
                                    const ulonglong2& v5, ull v6, int p) {
    if (p < 8)  return (p & 1) ? Hh.h[p >> 1].y : Hh.h[p >> 1].x;
    if (p == 8) return v4.x;
    if (p == 9) return v4.y;
    if (p == 10) return v5.x;
    if (p == 11) return v5.y;
    return v6;  // p == 12
}

// One ky step. cur.head already resident; loads cur tail early (c=0..2) and
// prefetches nxt.head (c=3..6) for the following ky.
__device__ __forceinline__ void ky_step(const Head& cur, Head& nxt,
                                        const float* rowCur, const float* rowNext,
                                        const ull* wrow,
                                        ull (&accA)[6], ull (&accB)[7]) {
    const ulonglong2* rc = (const ulonglong2*)rowCur;
    const ulonglong2* rn = (const ulonglong2*)rowNext;
    ulonglong2 v4, v5; ull v6;

    #pragma unroll
    for (int c = 0; c < 8; ++c) {
        // early operand staging (>=2 c-steps before first use)
        if (c == 0) v4 = rc[4];                         // P8,P9   (first use c=2)
        if (c == 1) v5 = rc[5];                         // P10,P11 (first use c=4)
        if (c == 2) v6 = *(const ull*)(rowCur + 24);    // P12     (first use c=6)
        if (c == 3) nxt.h[0] = rn[0];                   // next ky, first use c=0
        if (c == 4) nxt.h[1] = rn[1];
        if (c == 5) nxt.h[2] = rn[2];
        if (c == 6) nxt.h[3] = rn[3];

        const ulonglong2 wp = *(const ulonglong2*)(wrow + 2 * c); // (w_{2c}, w_{2c+1})

        #pragma unroll
        for (int j = 0; j < 6; ++j)
            accA[j] = fma2(wp.x, getP(cur, v4, v5, v6, j + c), accA[j]);
        if (c < 7) {
            #pragma unroll
            for (int j = 0; j < 7; ++j)
                accB[j] = fma2(wp.y, getP(cur, v4, v5, v6, j + c), accB[j]);
        }
    }
}

__global__ __launch_bounds__(NT, 3)
void conv2d_r11_kernel(const float* __restrict__ X,
                       const float* __restrict__ Wt,
                       const float* __restrict__ bias,
                       float* __restrict__ out)
{
    __shared__ __align__(16) float sX[IN_HP][SROW];
    __shared__ __align__(16) ull  sWp[KH * 16];   // (w,w) pairs, rows padded to 16

    const int tid = threadIdx.x;
    const int bx = blockIdx.x * BX;
    const int by = blockIdx.y * BY;

    // ---- stage weight pairs ----
    if (tid < KH * 16) {
        int r = tid >> 4, c = tid & 15;
        float w = (c < KW) ? Wt[r * KW + c] : 0.f;
        sWp[tid] = pack2(w, w);
    }

    // ---- stage input tile: 30 rows x 208 cols, float4, guarded ----
    const int NV = IN_H * (SROW / 4);     // 30*52 = 1560 (pad row 30 left unwritten)
    for (int idx = tid; idx < NV; idx += NT) {
        int r  = idx / (SROW / 4);
        int c4 = idx - r * (SROW / 4);
        int gr = by + r;
        int gc = bx + c4 * 4;
        float4 v = make_float4(0.f, 0.f, 0.f, 0.f);
        if (gr < H) {
            const float* src = X + (long)gr * W + gc;
            if (gc + 3 < W) v = *(const float4*)src;
            else {
                if (gc + 0 < W) v.x = src[0];
                if (gc + 1 < W) v.y = src[1];
                if (gc + 2 < W) v.z = src[2];
                if (gc + 3 < W) v.w = src[3];
            }
        }
        *(float4*)&sX[r][c4 * 4] = v;
    }
    __syncthreads();

    const int tx = tid & 15;
    const int ty = tid >> 4;
    const int ox = tx * RX;               // conflict-free, 16B aligned
    const float b0 = bias[0];

    ull accA[6];                          // (o_{2j}, o_{2j+1}); bias pre-folded
    ull accB[7];                          // (o_{2j-1}, o_{2j})
    {
        const ull bb = pack2(b0, b0);
        #pragma unroll
        for (int j = 0; j < 6; ++j) accA[j] = bb;
        #pragma unroll
        for (int j = 0; j < 7; ++j) accB[j] = 0ull;
    }

    Head A, B;
    {
        const ulonglong2* r0 = (const ulonglong2*)&sX[ty][ox];
        #pragma unroll
        for (int t = 0; t < 4; ++t) A.h[t] = r0[t];
    }

    const float* rowCur = &sX[ty][ox];
    const ull* wrow = sWp;

    // 15 ky steps, ping-ponged heads: even ky consumes A (fills B), odd consumes B.
    #pragma unroll 1
    for (int it = 0; it < 7; ++it) {
        ky_step(A, B, rowCur, rowCur + SROW, wrow, accA, accB);
        rowCur += SROW; wrow += 16;
        ky_step(B, A, rowCur, rowCur + SROW, wrow, accA, accB);
        rowCur += SROW; wrow += 16;
    }
    // ky = 14: next-row prefetch hits pad row 30 (in bounds, values unused)
    ky_step(A, B, rowCur, rowCur + SROW, wrow, accA, accB);

    // ---- epilogue: recombine phases, guarded float2 stores ----
    const int orow = by + ty;
    if (orow < OH) {
        float* orp = out + (long)orow * OW;
        float alo[6], ahi[6], blo[7], bhi[7];
        #pragma unroll
        for (int j = 0; j < 6; ++j) unpack2(accA[j], alo[j], ahi[j]);
        #pragma unroll
        for (int j = 0; j < 7; ++j) unpack2(accB[j], blo[j], bhi[j]);
        #pragma unroll
        for (int j = 0; j < 6; ++j) {
            int ocol = bx + ox + 2 * j;      // even; OW even -> pair fully in or out
            if (ocol < OW) {
                float2 st;
                st.x = alo[j] + bhi[j];          // o_{2j}   (bias in accA)
                st.y = ahi[j] + blo[j + 1];      // o_{2j+1}
                *(float2*)(orp + ocol) = st;
            }
        }
    }
}

extern "C" void kernel_launch(void* const* d_in, const int* in_sizes, int n_in,
                              void* d_out, int out_size)
{
    const float* X  = (const float*)d_in[0];
    const float* Wt = (const float*)d_in[1];
    const float* bs = (const float*)d_in[2];
    float* out = (float*)d_out;

    dim3 grid((OW + BX - 1) / BX, (OH + BY - 1) / BY);   // 22 x 256
    conv2d_r11_kernel<<<grid, NT>>>(X, Wt, bs, out);
}

// round 12
// speedup vs baseline: 1.4520x; 1.3059x over previous
#include <cuda_runtime.h>

// conv2d 4096x4096 (fp32) * 15x15 VALID + bias -> 4082x4082 (fp32)
// R12: R8 operating point (RY=1, RX=12, 4 blocks/SM, 32 warps) with
//      weights moved to __constant__ memory (LDC: dedicated constant port,
//      zero L1 crossbar wavefronts) and 2-4 c-step staging lead on the
//      rolling input window. Phase-shifted dual accumulators, FFMA2.

#define H 4096
#define W 4096
#define KH 15
#define KW 15
#define OH 4082
#define OW 4082

#define BX 192          // 16 threads * RX=12
#define BY 16
#define NT 256
#define RX 12           // 48B lane stride: odd multiple of 16B -> conflict-free

#define IN_H (BY + KH - 1)          // 30
#define SROW 208                    // pad 192+14 -> 208 (52 float4)

typedef unsigned long long ull;

__constant__ float cW[KH * KW];     // 225 floats, copied per launch (D2D memcpy node)

__device__ __forceinline__ ull pack2(float lo, float hi) {
    ull r; asm("mov.b64 %0, {%1, %2};" : "=l"(r) : "f"(lo), "f"(hi)); return r;
}
__device__ __forceinline__ void unpack2(ull v, float& lo, float& hi) {
    asm("mov.b64 {%0, %1}, %2;" : "=f"(lo), "=f"(hi) : "l"(v));
}
__device__ __forceinline__ ull fma2(ull a, ull b, ull c) {
    ull d; asm("fma.rn.f32x2 %0, %1, %2, %3;" : "=l"(d) : "l"(a), "l"(b), "l"(c)); return d;
}

__global__ __launch_bounds__(NT, 4)
void conv2d_r12_kernel(const float* __restrict__ X,
                       const float* __restrict__ bias,
                       float* __restrict__ out)
{
    __shared__ __align__(16) float sX[IN_H][SROW];

    const int tid = threadIdx.x;
    const int bx = blockIdx.x * BX;
    const int by = blockIdx.y * BY;

    // ---- stage input tile: 30 rows x 208 cols, float4, guarded ----
    const int NV = IN_H * (SROW / 4);     // 30*52 = 1560
    for (int idx = tid; idx < NV; idx += NT) {
        int r  = idx / (SROW / 4);
        int c4 = idx - r * (SROW / 4);
        int gr = by + r;
        int gc = bx + c4 * 4;
        float4 v = make_float4(0.f, 0.f, 0.f, 0.f);
        if (gr < H) {
            const float* src = X + (long)gr * W + gc;
            if (gc + 3 < W) v = *(const float4*)src;
            else {
                if (gc + 0 < W) v.x = src[0];
                if (gc + 1 < W) v.y = src[1];
                if (gc + 2 < W) v.z = src[2];
                if (gc + 3 < W) v.w = src[3];
            }
        }
        *(float4*)&sX[r][c4 * 4] = v;
    }
    __syncthreads();

    const int tx = tid & 15;
    const int ty = tid >> 4;
    const int ox = tx * RX;               // conflict-free, 16B aligned
    const float b0 = bias[0];

    ull accA[6];                          // (o_{2j}, o_{2j+1}); bias pre-folded
    ull accB[7];                          // (o_{2j-1}, o_{2j})
    {
        const ull bb = pack2(b0, b0);
        #pragma unroll
        for (int j = 0; j < 6; ++j) accA[j] = bb;
        #pragma unroll
        for (int j = 0; j < 7; ++j) accB[j] = 0ull;
    }

    #pragma unroll 1
    for (int ky = 0; ky < KH; ++ky) {
        const ulonglong2* row = (const ulonglong2*)&sX[ty + ky][ox];
        const float* rowf = &sX[ty + ky][ox];
        const int wb = ky * KW;

        // rolling window with staging lead:
        // v[0..3] up front; v4@c=0 (use c=2), v5@c=1 (use c=4), v6@c=2 (use c=6)
        ulonglong2 v[7];
        v[0] = row[0]; v[1] = row[1]; v[2] = row[2]; v[3] = row[3];

        #pragma unroll
        for (int c = 0; c < 8; ++c) {
            if (c == 0) v[4] = row[4];
            if (c == 1) v[5] = row[5];
            if (c == 2) v[6].x = *(const ull*)(rowf + 24);   // P12 (8B suffices)

            // weights from the constant port (no L1 wavefronts)
            const float we = cW[wb + 2 * c];
            const ull wpx = pack2(we, we);
            // even tap a=2c: accA[j] += w_{2c} * P[j+c], j=0..5
            #pragma unroll
            for (int j = 0; j < 6; ++j) {
                const int p = j + c;
                const ull Pp = (p & 1) ? v[p >> 1].y : v[p >> 1].x;
                accA[j] = fma2(wpx, Pp, accA[j]);
            }
            // odd tap a=2c+1: accB[j] += w_{2c+1} * P[j+c], j=0..6
            if (c < 7) {
                const float wo = cW[wb + 2 * c + 1];
                const ull wpy = pack2(wo, wo);
                #pragma unroll
                for (int j = 0; j < 7; ++j) {
                    const int p = j + c;
                    const ull Pp = (p & 1) ? v[p >> 1].y : v[p >> 1].x;
                    accB[j] = fma2(wpy, Pp, accB[j]);
                }
            }
        }
    }

    // ---- epilogue: recombine phases, guarded float2 stores ----
    const int orow = by + ty;
    if (orow < OH) {
        float* orp = out + (long)orow * OW;
        float alo[6], ahi[6], blo[7], bhi[7];
        #pragma unroll
        for (int j = 0; j < 6; ++j) unpack2(accA[j], alo[j], ahi[j]);
        #pragma unroll
        for (int j = 0; j < 7; ++j) unpack2(accB[j], blo[j], bhi[j]);
        #pragma unroll
        for (int j = 0; j < 6; ++j) {
            int ocol = bx + ox + 2 * j;      // even; OW even -> pair fully in or out
            if (ocol < OW) {
                float2 st;
                st.x = alo[j] + bhi[j];          // o_{2j}   (bias in accA)
                st.y = ahi[j] + blo[j + 1];      // o_{2j+1}
                *(float2*)(orp + ocol) = st;
            }
        }
    }
}

extern "C" void kernel_launch(void* const* d_in, const int* in_sizes, int n_in,
                              void* d_out, int out_size)
{
    const float* X  = (const float*)d_in[0];
    const float* Wt = (const float*)d_in[1];
    const float* bs = (const float*)d_in[2];
    float* out = (float*)d_out;

    // weights -> constant bank (device-to-device async copy; graph-capturable)
    cudaMemcpyToSymbolAsync(cW, Wt, KH * KW * sizeof(float), 0,
                            cudaMemcpyDeviceToDevice, 0);

    dim3 grid((OW + BX - 1) / BX, (OH + BY - 1) / BY);   // 22 x 256
    conv2d_r12_kernel<<<grid, NT>>>(X, bs, out);
}